// round 15
// baseline (speedup 1.0000x reference)
#include <cuda_runtime.h>
#include <cuda_fp16.h>

// Problem constants (fixed by the dataset)
#define Nn 50000
#define Ee 800000
#define Ff 128
#define Hh 256
#define Gg 512
#define Tt 5

#define NBLK 196   // ceil(Nn/256) scan blocks

// W16 offsets (halves), [k][n] layout (row-major, n stride 256)
#define W0OFF 0
#define W1OFF 32768
#define W2OFF 98304
#define W3OFF 163840
#define WTOT  229376

// ---------------- scratch (device globals; no allocations allowed) ----------
__device__ int    g_cnt[Nn];
__device__ int    g_rowptr[Nn + 1];
__device__ int    g_cursor[Nn];
__device__ int    g_col[Ee];
__device__ float  g_dinv[Nn];
__device__ int    g_bsum[NBLK];
__device__ int    g_boff[NBLK];
__device__ __half g_W16[WTOT];               // fp16 weights, [k][n]
__device__ __half g_bufA[(size_t)Nn * Hh];   // ping (features, fp16)
__device__ __half g_bufB[(size_t)Nn * Hh];   // pong (aggregation output, fp16)
__device__ float  g_pool[Gg * Hh];
__device__ float  g_cnts[Gg];

// ---------------- prep kernels ----------------------------------------------
// zero + weight conversion fused (all independent elementwise)
__global__ void zero_wconv_kernel(const float* __restrict__ W0,
                                  const float* __restrict__ W1,
                                  const float* __restrict__ W2,
                                  const float* __restrict__ W3) {
    int i = blockIdx.x * blockDim.x + threadIdx.x;
    if (i < Nn) g_cnt[i] = 0;
    if (i < Gg * Hh) g_pool[i] = 0.0f;
    if (i < Gg) g_cnts[i] = 0.0f;
    if (i < WTOT) {
        const float* p; int off;
        if (i < W1OFF)      { p = W0; off = W0OFF; }
        else if (i < W2OFF) { p = W1; off = W1OFF; }
        else if (i < W3OFF) { p = W2; off = W2OFF; }
        else                { p = W3; off = W3OFF; }
        g_W16[i] = __float2half_rn(p[i - off]);
    }
}

__global__ void hist_kernel(const int4* __restrict__ dst4) {
    int e = blockIdx.x * blockDim.x + threadIdx.x;
    if (e < Ee / 4) {
        int4 d = dst4[e];
        if (d.x >= 0 && d.x < Nn) atomicAdd(&g_cnt[d.x], 1);
        if (d.y >= 0 && d.y < Nn) atomicAdd(&g_cnt[d.y], 1);
        if (d.z >= 0 && d.z < Nn) atomicAdd(&g_cnt[d.z], 1);
        if (d.w >= 0 && d.w < Nn) atomicAdd(&g_cnt[d.w], 1);
    }
}

// hierarchical scan: block sums -> scan sums -> per-block rescan
__global__ void scan1_kernel() {
    __shared__ int wsum[8];
    int tid = threadIdx.x, lane = tid & 31, wid = tid >> 5;
    int i = blockIdx.x * 256 + tid;
    int v = (i < Nn) ? g_cnt[i] : 0;
#pragma unroll
    for (int d = 16; d; d >>= 1) v += __shfl_down_sync(0xffffffffu, v, d);
    if (lane == 0) wsum[wid] = v;
    __syncthreads();
    if (tid == 0) {
        int s = 0;
#pragma unroll
        for (int w = 0; w < 8; w++) s += wsum[w];
        g_bsum[blockIdx.x] = s;
    }
}

__global__ void scan2_kernel() {
    __shared__ int s[256];
    int tid = threadIdx.x;
    int v = (tid < NBLK) ? g_bsum[tid] : 0;
    s[tid] = v;
    __syncthreads();
    for (int d = 1; d < 256; d <<= 1) {
        int t = (tid >= d) ? s[tid - d] : 0;
        __syncthreads();
        s[tid] += t;
        __syncthreads();
    }
    if (tid < NBLK) g_boff[tid] = s[tid] - v;   // exclusive
    if (tid == NBLK - 1) g_rowptr[Nn] = s[tid];
}

// scan3 also: dinv, per-graph counts, cursor zero
__global__ void scan3_kernel(const int* __restrict__ batch) {
    __shared__ int wsum[8];
    int tid = threadIdx.x, lane = tid & 31, wid = tid >> 5;
    int i = blockIdx.x * 256 + tid;
    int orig = (i < Nn) ? g_cnt[i] : 0;
    int v = orig;
#pragma unroll
    for (int d = 1; d < 32; d <<= 1) {
        int t = __shfl_up_sync(0xffffffffu, v, d);
        if (lane >= d) v += t;
    }
    if (lane == 31) wsum[wid] = v;
    __syncthreads();
    if (wid == 0 && lane < 8) {
        int s = wsum[lane];
#pragma unroll
        for (int d = 1; d < 8; d <<= 1) {
            int t = __shfl_up_sync(0x000000ffu, s, d);
            if (lane >= d) s += t;
        }
        wsum[lane] = s;
    }
    __syncthreads();
    int prefix = (wid > 0) ? wsum[wid - 1] : 0;
    if (i < Nn) {
        g_rowptr[i] = g_boff[blockIdx.x] + prefix + v - orig;
        g_cursor[i] = 0;
        g_dinv[i] = rsqrtf((float)(orig + 1));   // +1 self-loop
        int g = batch[i];
        if (g >= 0 && g < Gg) atomicAdd(&g_cnts[g], 1.0f);
    }
}

__global__ void fill_kernel(const int4* __restrict__ src4,
                            const int4* __restrict__ dst4) {
    int e = blockIdx.x * blockDim.x + threadIdx.x;
    if (e < Ee / 4) {
        int4 d = dst4[e];
        int4 s = src4[e];
#pragma unroll
        for (int j = 0; j < 4; j++) {
            int dd = (&d.x)[j], ss = (&s.x)[j];
            if (dd >= 0 && dd < Nn && ss >= 0 && ss < Nn) {
                int pos = g_rowptr[dd] + atomicAdd(&g_cursor[dd], 1);
                g_col[pos] = ss;
            }
        }
    }
}

// bufA(fp16) = x * dinv[row]   (width Ff); each thread handles 8 floats
__global__ void scale_x_kernel(const float4* __restrict__ x) {
    int idx = blockIdx.x * blockDim.x + threadIdx.x;   // over Nn * 16
    if (idx < Nn * (Ff / 8)) {
        int row = idx >> 4;
        float d = g_dinv[row];
        float4 v0 = x[idx * 2], v1 = x[idx * 2 + 1];
        __half2 h[4];
        h[0] = __floats2half2_rn(v0.x * d, v0.y * d);
        h[1] = __floats2half2_rn(v0.z * d, v0.w * d);
        h[2] = __floats2half2_rn(v1.x * d, v1.y * d);
        h[3] = __floats2half2_rn(v1.z * d, v1.w * d);
        ((uint4*)g_bufA)[idx] = *(uint4*)h;
    }
}

// ---------------- aggregation ------------------------------------------------
// Layer 0 (width 128): one warp per node, uint2 per lane (R9 exact).
__global__ void agg128_kernel() {
    int warp = (blockIdx.x * blockDim.x + threadIdx.x) >> 5;
    int lane = threadIdx.x & 31;
    if (warp >= Nn) return;
    const uint2* __restrict__ hs = (const uint2*)g_bufA;   // row = 32 uint2
    uint2* __restrict__ outp = (uint2*)g_bufB;

    float f[4];
    {
        uint2 v = hs[(size_t)warp * 32 + lane];
        const unsigned* u = (const unsigned*)&v;
#pragma unroll
        for (int h = 0; h < 2; h++) {
            float2 p = __half22float2(*(const __half2*)&u[h]);
            f[2 * h] = p.x; f[2 * h + 1] = p.y;
        }
    }
    int beg = g_rowptr[warp], end = g_rowptr[warp + 1];
    int e = beg;
    for (; e + 1 < end; e += 2) {
        int s0 = g_col[e], s1 = g_col[e + 1];
        uint2 v0 = hs[(size_t)s0 * 32 + lane];
        uint2 v1 = hs[(size_t)s1 * 32 + lane];
        const unsigned* u0 = (const unsigned*)&v0;
        const unsigned* u1 = (const unsigned*)&v1;
#pragma unroll
        for (int h = 0; h < 2; h++) {
            float2 p0 = __half22float2(*(const __half2*)&u0[h]);
            float2 p1 = __half22float2(*(const __half2*)&u1[h]);
            f[2 * h] += p0.x + p1.x;
            f[2 * h + 1] += p0.y + p1.y;
        }
    }
    if (e < end) {
        int s0 = g_col[e];
        uint2 v0 = hs[(size_t)s0 * 32 + lane];
        const unsigned* u0 = (const unsigned*)&v0;
#pragma unroll
        for (int h = 0; h < 2; h++) {
            float2 p0 = __half22float2(*(const __half2*)&u0[h]);
            f[2 * h] += p0.x;
            f[2 * h + 1] += p0.y;
        }
    }
    float di = g_dinv[warp];
    uint2 ov;
    unsigned* ou = (unsigned*)&ov;
#pragma unroll
    for (int h = 0; h < 2; h++) {
        __half2 p = __floats2half2_rn(f[2 * h] * di, f[2 * h + 1] * di);
        ou[h] = *(unsigned*)&p;
    }
    outp[(size_t)warp * 32 + lane] = ov;
}

// Width 256: TWO warps per node, each handles a half-row (128 halves,
// uint2 per lane). Same bytes, 2x warps, halved straggler cost.
__global__ void agg256_half_kernel() {
    int w = (blockIdx.x * blockDim.x + threadIdx.x) >> 5;
    int lane = threadIdx.x & 31;
    int node = w >> 1;
    int half = w & 1;
    if (node >= Nn) return;
    const uint2* __restrict__ hs = (const uint2*)g_bufA;   // row = 64 uint2
    uint2* __restrict__ outp = (uint2*)g_bufB;
    int off = half * 32 + lane;                            // uint2 index in row

    float f[4];
    {
        uint2 v = hs[(size_t)node * 64 + off];             // self-loop
        const unsigned* u = (const unsigned*)&v;
#pragma unroll
        for (int h = 0; h < 2; h++) {
            float2 p = __half22float2(*(const __half2*)&u[h]);
            f[2 * h] = p.x; f[2 * h + 1] = p.y;
        }
    }
    int beg = g_rowptr[node], end = g_rowptr[node + 1];
    int e = beg;
    for (; e + 1 < end; e += 2) {
        int s0 = g_col[e], s1 = g_col[e + 1];
        uint2 v0 = hs[(size_t)s0 * 64 + off];
        uint2 v1 = hs[(size_t)s1 * 64 + off];
        const unsigned* u0 = (const unsigned*)&v0;
        const unsigned* u1 = (const unsigned*)&v1;
#pragma unroll
        for (int h = 0; h < 2; h++) {
            float2 p0 = __half22float2(*(const __half2*)&u0[h]);
            float2 p1 = __half22float2(*(const __half2*)&u1[h]);
            f[2 * h] += p0.x + p1.x;
            f[2 * h + 1] += p0.y + p1.y;
        }
    }
    if (e < end) {
        int s0 = g_col[e];
        uint2 v0 = hs[(size_t)s0 * 64 + off];
        const unsigned* u0 = (const unsigned*)&v0;
#pragma unroll
        for (int h = 0; h < 2; h++) {
            float2 p0 = __half22float2(*(const __half2*)&u0[h]);
            f[2 * h] += p0.x;
            f[2 * h + 1] += p0.y;
        }
    }
    float di = g_dinv[node];
    uint2 ov;
    unsigned* ou = (unsigned*)&ov;
#pragma unroll
    for (int h = 0; h < 2; h++) {
        __half2 p = __floats2half2_rn(f[2 * h] * di, f[2 * h + 1] * di);
        ou[h] = *(unsigned*)&p;
    }
    outp[(size_t)node * 64 + off] = ov;
}

// ---------------- fp16 tensor-core GEMM (R9 exact: BN=128, reg prefetch) -----
#define BM 128
#define BN 128
#define BK 32
#define ASTR 40    // A smem row stride (halves)
#define BNP 136    // B smem row stride (halves)

__device__ __forceinline__ void mma_f16(float* c, const unsigned* a, const unsigned* b) {
    asm volatile(
        "mma.sync.aligned.m16n8k16.row.col.f32.f16.f16.f32 "
        "{%0,%1,%2,%3}, {%4,%5,%6,%7}, {%8,%9}, {%0,%1,%2,%3};"
        : "+f"(c[0]), "+f"(c[1]), "+f"(c[2]), "+f"(c[3])
        : "r"(a[0]), "r"(a[1]), "r"(a[2]), "r"(a[3]), "r"(b[0]), "r"(b[1]));
}

__device__ __forceinline__ void ldsm_x2_trans(unsigned& r0, unsigned& r1, const void* p) {
    unsigned addr = (unsigned)__cvta_generic_to_shared(p);
    asm volatile("ldmatrix.sync.aligned.m8n8.x2.trans.shared.b16 {%0,%1}, [%2];"
                 : "=r"(r0), "=r"(r1) : "r"(addr));
}

__global__ __launch_bounds__(256)
void gemm_f16_kernel(const __half* __restrict__ Wk,   // [K][256] fp16
                     const float* __restrict__ bias,
                     int K, int scaleFlag, int poolFlag,
                     const int* __restrict__ batch) {
    __shared__ alignas(16) __half As[BM][ASTR];   // [m][k]
    __shared__ alignas(16) __half Bs[BK][BNP];    // [k][n]

    const __half* __restrict__ A = g_bufB;
    __half* __restrict__ C = g_bufA;

    int tid = threadIdx.x;
    int warpId = tid >> 5, lane = tid & 31;
    int g = lane >> 2, q = lane & 3;
    int warpM = warpId >> 2;          // 0..1  -> 64 rows each
    int warpN = warpId & 3;           // 0..3  -> 32 cols each
    int rowBase = blockIdx.x * BM;
    int colBase = blockIdx.y * BN;

    float acc[4][4][4];
#pragma unroll
    for (int mt = 0; mt < 4; mt++)
#pragma unroll
        for (int nt = 0; nt < 4; nt++)
#pragma unroll
            for (int i = 0; i < 4; i++) acc[mt][nt][i] = 0.0f;

    // A-load indices
    int aRow = tid >> 1;              // 0..127
    int aKoff = (tid & 1) * 16;       // halves
    // B-load indices: coalesced [k][n] copy
    int bK = tid >> 4;                // 0..15
    int bN8 = (tid & 15) * 8;         // n offset, 8 halves per thread

    int gr = rowBase + aRow;
    bool aOk = gr < Nn;
    const __half* aSrc = A + (size_t)gr * K + aKoff;
    const __half* bSrc0 = Wk + (size_t)bK * Hh + colBase + bN8;
    const __half* bSrc1 = Wk + (size_t)(bK + 16) * Hh + colBase + bN8;

    int niter = K / BK;

    // prologue: load iter 0 into regs
    uint4 av0 = make_uint4(0, 0, 0, 0), av1 = av0;
    if (aOk) {
        const uint4* ap = (const uint4*)aSrc;
        av0 = ap[0]; av1 = ap[1];
    }
    uint4 bv0 = *(const uint4*)bSrc0;
    uint4 bv1 = *(const uint4*)bSrc1;

    for (int it = 0; it < niter; it++) {
        // regs -> smem
        *(uint4*)&As[aRow][aKoff] = av0;
        *(uint4*)&As[aRow][aKoff + 8] = av1;
        *(uint4*)&Bs[bK][bN8] = bv0;
        *(uint4*)&Bs[bK + 16][bN8] = bv1;
        __syncthreads();

        // prefetch next iter while computing this one
        if (it + 1 < niter) {
            int k0 = (it + 1) * BK;
            if (aOk) {
                const uint4* ap = (const uint4*)(aSrc + k0);
                av0 = ap[0]; av1 = ap[1];
            }
            bv0 = *(const uint4*)(bSrc0 + (size_t)k0 * Hh);
            bv1 = *(const uint4*)(bSrc1 + (size_t)k0 * Hh);
        }

#pragma unroll
        for (int kk = 0; kk < 2; kk++) {
            int kb = kk * 16;
            unsigned afr[4][4];
#pragma unroll
            for (int mt = 0; mt < 4; mt++) {
                int m = warpM * 64 + mt * 16;
                afr[mt][0] = *(const unsigned*)&As[m + g][kb + 2 * q];
                afr[mt][1] = *(const unsigned*)&As[m + g + 8][kb + 2 * q];
                afr[mt][2] = *(const unsigned*)&As[m + g][kb + 2 * q + 8];
                afr[mt][3] = *(const unsigned*)&As[m + g + 8][kb + 2 * q + 8];
            }
#pragma unroll
            for (int nt = 0; nt < 4; nt++) {
                int n0 = warpN * 32 + nt * 8;
                unsigned bfr[2];
                ldsm_x2_trans(bfr[0], bfr[1], &Bs[kb + (lane & 15)][n0]);
#pragma unroll
                for (int mt = 0; mt < 4; mt++)
                    mma_f16(acc[mt][nt], afr[mt], bfr);
            }
        }
        __syncthreads();
    }

    // ---- epilogue ----
#pragma unroll
    for (int mt = 0; mt < 4; mt++) {
        int r0 = rowBase + warpM * 64 + mt * 16 + g;
        int r1 = r0 + 8;
        bool ok0 = r0 < Nn, ok1 = r1 < Nn;
        float sc0 = (ok0 && scaleFlag) ? g_dinv[r0] : 1.0f;
        float sc1 = (ok1 && scaleFlag) ? g_dinv[r1] : 1.0f;
        int gb0 = (ok0 && poolFlag) ? batch[r0] : 0;
        int gb1 = (ok1 && poolFlag) ? batch[r1] : 0;
#pragma unroll
        for (int nt = 0; nt < 4; nt++) {
            int c = colBase + warpN * 32 + nt * 8 + 2 * q;
            float bs0 = bias[c], bs1 = bias[c + 1];
            float v00 = fmaxf(acc[mt][nt][0] + bs0, 0.0f) * sc0;
            float v01 = fmaxf(acc[mt][nt][1] + bs1, 0.0f) * sc0;
            float v10 = fmaxf(acc[mt][nt][2] + bs0, 0.0f) * sc1;
            float v11 = fmaxf(acc[mt][nt][3] + bs1, 0.0f) * sc1;
            if (poolFlag) {
                if (ok0) {
                    atomicAdd(&g_pool[gb0 * Hh + c], v00);
                    atomicAdd(&g_pool[gb0 * Hh + c + 1], v01);
                }
                if (ok1) {
                    atomicAdd(&g_pool[gb1 * Hh + c], v10);
                    atomicAdd(&g_pool[gb1 * Hh + c + 1], v11);
                }
            } else {
                if (ok0) {
                    __half2 h = __floats2half2_rn(v00, v01);
                    *(__half2*)&C[(size_t)r0 * Hh + c] = h;
                }
                if (ok1) {
                    __half2 h = __floats2half2_rn(v10, v11);
                    *(__half2*)&C[(size_t)r1 * Hh + c] = h;
                }
            }
        }
    }
}

// ---------------- output head -------------------------------------------------
__global__ void out_kernel(const float* __restrict__ Wout,
                           const float* __restrict__ bout,
                           float* __restrict__ out) {
    int g = blockIdx.x;
    int lane = threadIdx.x;                 // 32 threads
    float inv = 1.0f / fmaxf(g_cnts[g], 1.0f);
    float p[8];
#pragma unroll
    for (int v = 0; v < 8; v++) p[v] = g_pool[g * Hh + v * 32 + lane] * inv;
#pragma unroll
    for (int t = 0; t < Tt; t++) {
        float s = 0.0f;
#pragma unroll
        for (int v = 0; v < 8; v++) s += p[v] * Wout[(v * 32 + lane) * Tt + t];
#pragma unroll
        for (int off = 16; off; off >>= 1) s += __shfl_down_sync(0xffffffffu, s, off);
        if (lane == 0) out[g * Tt + t] = s + bout[t];
    }
}

// ---------------- launch -----------------------------------------------------
extern "C" void kernel_launch(void* const* d_in, const int* in_sizes, int n_in,
                              void* d_out, int out_size) {
    const float* x    = (const float*)d_in[0];
    const int*   ei   = (const int*)d_in[1];   // [2, E] int32
    const int*   bat  = (const int*)d_in[2];
    const float* W0 = (const float*)d_in[3];  const float* b0 = (const float*)d_in[4];
    const float* W1 = (const float*)d_in[5];  const float* b1 = (const float*)d_in[6];
    const float* W2 = (const float*)d_in[7];  const float* b2 = (const float*)d_in[8];
    const float* W3 = (const float*)d_in[9];  const float* b3 = (const float*)d_in[10];
    const float* Wout = (const float*)d_in[11]; const float* bout = (const float*)d_in[12];
    float* out = (float*)d_out;

    const int* src = ei;
    const int* dst = ei + Ee;

    // prep (R9 exact)
    zero_wconv_kernel<<<(WTOT + 255) / 256, 256>>>(W0, W1, W2, W3);
    hist_kernel<<<(Ee / 4 + 255) / 256, 256>>>((const int4*)dst);
    scan1_kernel<<<NBLK, 256>>>();
    scan2_kernel<<<1, 256>>>();
    scan3_kernel<<<NBLK, 256>>>(bat);
    fill_kernel<<<(Ee / 4 + 255) / 256, 256>>>((const int4*)src, (const int4*)dst);
    scale_x_kernel<<<(Nn * (Ff / 8) + 255) / 256, 256>>>((const float4*)x);

    dim3 gemmGrid((Nn + BM - 1) / BM, Hh / BN);
    int aggBlocks128 = (Nn * 32 + 255) / 256;
    int aggBlocks256 = (Nn * 64 + 255) / 256;   // 2 warps per node

    __half* W16;
    cudaGetSymbolAddress((void**)&W16, g_W16);

    // layer 0 (K=128)
    agg128_kernel<<<aggBlocks128, 256>>>();
    gemm_f16_kernel<<<gemmGrid, 256>>>(W16 + W0OFF, b0, Ff, 1, 0, bat);
    // layer 1
    agg256_half_kernel<<<aggBlocks256, 256>>>();
    gemm_f16_kernel<<<gemmGrid, 256>>>(W16 + W1OFF, b1, Hh, 1, 0, bat);
    // layer 2
    agg256_half_kernel<<<aggBlocks256, 256>>>();
    gemm_f16_kernel<<<gemmGrid, 256>>>(W16 + W2OFF, b2, Hh, 1, 0, bat);
    // layer 3: no dinv pre-scale; fused mean-pool accumulation
    agg256_half_kernel<<<aggBlocks256, 256>>>();
    gemm_f16_kernel<<<gemmGrid, 256>>>(W16 + W3OFF, b3, Hh, 0, 1, bat);

    // head
    out_kernel<<<Gg, 32>>>(Wout, bout, out);
}

// round 16
// speedup vs baseline: 1.1046x; 1.1046x over previous
#include <cuda_runtime.h>
#include <cuda_fp16.h>

// Problem constants (fixed by the dataset)
#define Nn 50000
#define Ee 800000
#define Ff 128
#define Hh 256
#define Gg 512
#define Tt 5

#define NBLK 196   // ceil(Nn/256) scan blocks

// W16 offsets (halves), [k][n] layout (row-major, n stride 256)
#define W0OFF 0
#define W1OFF 32768
#define W2OFF 98304
#define W3OFF 163840
#define WTOT  229376

// ---------------- scratch (device globals; no allocations allowed) ----------
__device__ int    g_cnt[Nn];
__device__ int    g_rowptr[Nn + 1];
__device__ int    g_cursor[Nn];
__device__ int    g_col[Ee];
__device__ float  g_dinv[Nn];
__device__ int    g_bsum[NBLK];
__device__ int    g_boff[NBLK];
__device__ __half g_W16[WTOT];               // fp16 weights, [k][n]
__device__ __half g_bufA[(size_t)Nn * Hh];   // ping (features, fp16)
__device__ __half g_bufB[(size_t)Nn * Hh];   // pong (aggregation output, fp16)
__device__ float  g_pool[Gg * Hh];
__device__ float  g_cnts[Gg];

// ---------------- prep kernels ----------------------------------------------
// zero + weight conversion fused (all independent elementwise)
__global__ void zero_wconv_kernel(const float* __restrict__ W0,
                                  const float* __restrict__ W1,
                                  const float* __restrict__ W2,
                                  const float* __restrict__ W3) {
    int i = blockIdx.x * blockDim.x + threadIdx.x;
    if (i < Nn) g_cnt[i] = 0;
    if (i < Gg * Hh) g_pool[i] = 0.0f;
    if (i < Gg) g_cnts[i] = 0.0f;
    if (i < WTOT) {
        const float* p; int off;
        if (i < W1OFF)      { p = W0; off = W0OFF; }
        else if (i < W2OFF) { p = W1; off = W1OFF; }
        else if (i < W3OFF) { p = W2; off = W2OFF; }
        else                { p = W3; off = W3OFF; }
        g_W16[i] = __float2half_rn(p[i - off]);
    }
}

__global__ void hist_kernel(const int4* __restrict__ dst4) {
    int e = blockIdx.x * blockDim.x + threadIdx.x;
    if (e < Ee / 4) {
        int4 d = dst4[e];
        if (d.x >= 0 && d.x < Nn) atomicAdd(&g_cnt[d.x], 1);
        if (d.y >= 0 && d.y < Nn) atomicAdd(&g_cnt[d.y], 1);
        if (d.z >= 0 && d.z < Nn) atomicAdd(&g_cnt[d.z], 1);
        if (d.w >= 0 && d.w < Nn) atomicAdd(&g_cnt[d.w], 1);
    }
}

// hierarchical scan: block sums -> scan sums -> per-block rescan
__global__ void scan1_kernel() {
    __shared__ int wsum[8];
    int tid = threadIdx.x, lane = tid & 31, wid = tid >> 5;
    int i = blockIdx.x * 256 + tid;
    int v = (i < Nn) ? g_cnt[i] : 0;
#pragma unroll
    for (int d = 16; d; d >>= 1) v += __shfl_down_sync(0xffffffffu, v, d);
    if (lane == 0) wsum[wid] = v;
    __syncthreads();
    if (tid == 0) {
        int s = 0;
#pragma unroll
        for (int w = 0; w < 8; w++) s += wsum[w];
        g_bsum[blockIdx.x] = s;
    }
}

__global__ void scan2_kernel() {
    __shared__ int s[256];
    int tid = threadIdx.x;
    int v = (tid < NBLK) ? g_bsum[tid] : 0;
    s[tid] = v;
    __syncthreads();
    for (int d = 1; d < 256; d <<= 1) {
        int t = (tid >= d) ? s[tid - d] : 0;
        __syncthreads();
        s[tid] += t;
        __syncthreads();
    }
    if (tid < NBLK) g_boff[tid] = s[tid] - v;   // exclusive
    if (tid == NBLK - 1) g_rowptr[Nn] = s[tid];
}

// scan3 also: dinv, per-graph counts, cursor zero
__global__ void scan3_kernel(const int* __restrict__ batch) {
    __shared__ int wsum[8];
    int tid = threadIdx.x, lane = tid & 31, wid = tid >> 5;
    int i = blockIdx.x * 256 + tid;
    int orig = (i < Nn) ? g_cnt[i] : 0;
    int v = orig;
#pragma unroll
    for (int d = 1; d < 32; d <<= 1) {
        int t = __shfl_up_sync(0xffffffffu, v, d);
        if (lane >= d) v += t;
    }
    if (lane == 31) wsum[wid] = v;
    __syncthreads();
    if (wid == 0 && lane < 8) {
        int s = wsum[lane];
#pragma unroll
        for (int d = 1; d < 8; d <<= 1) {
            int t = __shfl_up_sync(0x000000ffu, s, d);
            if (lane >= d) s += t;
        }
        wsum[lane] = s;
    }
    __syncthreads();
    int prefix = (wid > 0) ? wsum[wid - 1] : 0;
    if (i < Nn) {
        g_rowptr[i] = g_boff[blockIdx.x] + prefix + v - orig;
        g_cursor[i] = 0;
        g_dinv[i] = rsqrtf((float)(orig + 1));   // +1 self-loop
        int g = batch[i];
        if (g >= 0 && g < Gg) atomicAdd(&g_cnts[g], 1.0f);
    }
}

__global__ void fill_kernel(const int4* __restrict__ src4,
                            const int4* __restrict__ dst4) {
    int e = blockIdx.x * blockDim.x + threadIdx.x;
    if (e < Ee / 4) {
        int4 d = dst4[e];
        int4 s = src4[e];
#pragma unroll
        for (int j = 0; j < 4; j++) {
            int dd = (&d.x)[j], ss = (&s.x)[j];
            if (dd >= 0 && dd < Nn && ss >= 0 && ss < Nn) {
                int pos = g_rowptr[dd] + atomicAdd(&g_cursor[dd], 1);
                g_col[pos] = ss;
            }
        }
    }
}

// bufA(fp16) = x * dinv[row]   (width Ff); each thread handles 8 floats
__global__ void scale_x_kernel(const float4* __restrict__ x) {
    int idx = blockIdx.x * blockDim.x + threadIdx.x;   // over Nn * 16
    if (idx < Nn * (Ff / 8)) {
        int row = idx >> 4;
        float d = g_dinv[row];
        float4 v0 = x[idx * 2], v1 = x[idx * 2 + 1];
        __half2 h[4];
        h[0] = __floats2half2_rn(v0.x * d, v0.y * d);
        h[1] = __floats2half2_rn(v0.z * d, v0.w * d);
        h[2] = __floats2half2_rn(v1.x * d, v1.y * d);
        h[3] = __floats2half2_rn(v1.z * d, v1.w * d);
        ((uint4*)g_bufA)[idx] = *(uint4*)h;
    }
}

// ---------------- aggregation (fp16 in, fp32 accum, fp16 out) ---------------
// One warp per node, 2-wide edge unroll (R9 exact — measured best).
template <int UC> struct VecT;
template <> struct VecT<2> { using T = uint2; };
template <> struct VecT<4> { using T = uint4; };

template <int VH>
__global__ void agg_kernel() {
    constexpr int UC = VH / 2;
    using V = typename VecT<UC>::T;
    int warp = (blockIdx.x * blockDim.x + threadIdx.x) >> 5;
    int lane = threadIdx.x & 31;
    if (warp >= Nn) return;
    const V* __restrict__ hs = (const V*)g_bufA;   // row = 32 V units
    V* __restrict__ outp = (V*)g_bufB;

    float f[VH];
    {
        V v = hs[(size_t)warp * 32 + lane];        // self-loop term
        const unsigned* u = (const unsigned*)&v;
#pragma unroll
        for (int h = 0; h < UC; h++) {
            float2 p = __half22float2(*(const __half2*)&u[h]);
            f[2 * h] = p.x; f[2 * h + 1] = p.y;
        }
    }

    int beg = g_rowptr[warp], end = g_rowptr[warp + 1];
    int e = beg;
    for (; e + 1 < end; e += 2) {
        int s0 = g_col[e], s1 = g_col[e + 1];
        V v0 = hs[(size_t)s0 * 32 + lane];
        V v1 = hs[(size_t)s1 * 32 + lane];
        const unsigned* u0 = (const unsigned*)&v0;
        const unsigned* u1 = (const unsigned*)&v1;
#pragma unroll
        for (int h = 0; h < UC; h++) {
            float2 p0 = __half22float2(*(const __half2*)&u0[h]);
            float2 p1 = __half22float2(*(const __half2*)&u1[h]);
            f[2 * h] += p0.x + p1.x;
            f[2 * h + 1] += p0.y + p1.y;
        }
    }
    if (e < end) {
        int s0 = g_col[e];
        V v0 = hs[(size_t)s0 * 32 + lane];
        const unsigned* u0 = (const unsigned*)&v0;
#pragma unroll
        for (int h = 0; h < UC; h++) {
            float2 p0 = __half22float2(*(const __half2*)&u0[h]);
            f[2 * h] += p0.x;
            f[2 * h + 1] += p0.y;
        }
    }
    float di = g_dinv[warp];
    V ov;
    unsigned* ou = (unsigned*)&ov;
#pragma unroll
    for (int h = 0; h < UC; h++) {
        __half2 p = __floats2half2_rn(f[2 * h] * di, f[2 * h + 1] * di);
        ou[h] = *(unsigned*)&p;
    }
    outp[(size_t)warp * 32 + lane] = ov;
}

// ---------------- fp16 tensor-core GEMM (R9 exact: BN=128, reg prefetch) -----
#define BM 128
#define BN 128
#define BK 32
#define ASTR 40    // A smem row stride (halves)
#define BNP 136    // B smem row stride (halves)

__device__ __forceinline__ void mma_f16(float* c, const unsigned* a, const unsigned* b) {
    asm volatile(
        "mma.sync.aligned.m16n8k16.row.col.f32.f16.f16.f32 "
        "{%0,%1,%2,%3}, {%4,%5,%6,%7}, {%8,%9}, {%0,%1,%2,%3};"
        : "+f"(c[0]), "+f"(c[1]), "+f"(c[2]), "+f"(c[3])
        : "r"(a[0]), "r"(a[1]), "r"(a[2]), "r"(a[3]), "r"(b[0]), "r"(b[1]));
}

__device__ __forceinline__ void ldsm_x2_trans(unsigned& r0, unsigned& r1, const void* p) {
    unsigned addr = (unsigned)__cvta_generic_to_shared(p);
    asm volatile("ldmatrix.sync.aligned.m8n8.x2.trans.shared.b16 {%0,%1}, [%2];"
                 : "=r"(r0), "=r"(r1) : "r"(addr));
}

__global__ __launch_bounds__(256)
void gemm_f16_kernel(const __half* __restrict__ Wk,   // [K][256] fp16
                     const float* __restrict__ bias,
                     int K, int scaleFlag, int poolFlag,
                     const int* __restrict__ batch) {
    __shared__ alignas(16) __half As[BM][ASTR];   // [m][k]
    __shared__ alignas(16) __half Bs[BK][BNP];    // [k][n]

    const __half* __restrict__ A = g_bufB;
    __half* __restrict__ C = g_bufA;

    int tid = threadIdx.x;
    int warpId = tid >> 5, lane = tid & 31;
    int g = lane >> 2, q = lane & 3;
    int warpM = warpId >> 2;          // 0..1  -> 64 rows each
    int warpN = warpId & 3;           // 0..3  -> 32 cols each
    int rowBase = blockIdx.x * BM;
    int colBase = blockIdx.y * BN;

    float acc[4][4][4];
#pragma unroll
    for (int mt = 0; mt < 4; mt++)
#pragma unroll
        for (int nt = 0; nt < 4; nt++)
#pragma unroll
            for (int i = 0; i < 4; i++) acc[mt][nt][i] = 0.0f;

    // A-load indices
    int aRow = tid >> 1;              // 0..127
    int aKoff = (tid & 1) * 16;       // halves
    // B-load indices: coalesced [k][n] copy
    int bK = tid >> 4;                // 0..15
    int bN8 = (tid & 15) * 8;         // n offset, 8 halves per thread

    int gr = rowBase + aRow;
    bool aOk = gr < Nn;
    const __half* aSrc = A + (size_t)gr * K + aKoff;
    const __half* bSrc0 = Wk + (size_t)bK * Hh + colBase + bN8;
    const __half* bSrc1 = Wk + (size_t)(bK + 16) * Hh + colBase + bN8;

    int niter = K / BK;

    // prologue: load iter 0 into regs
    uint4 av0 = make_uint4(0, 0, 0, 0), av1 = av0;
    if (aOk) {
        const uint4* ap = (const uint4*)aSrc;
        av0 = ap[0]; av1 = ap[1];
    }
    uint4 bv0 = *(const uint4*)bSrc0;
    uint4 bv1 = *(const uint4*)bSrc1;

    for (int it = 0; it < niter; it++) {
        // regs -> smem
        *(uint4*)&As[aRow][aKoff] = av0;
        *(uint4*)&As[aRow][aKoff + 8] = av1;
        *(uint4*)&Bs[bK][bN8] = bv0;
        *(uint4*)&Bs[bK + 16][bN8] = bv1;
        __syncthreads();

        // prefetch next iter while computing this one
        if (it + 1 < niter) {
            int k0 = (it + 1) * BK;
            if (aOk) {
                const uint4* ap = (const uint4*)(aSrc + k0);
                av0 = ap[0]; av1 = ap[1];
            }
            bv0 = *(const uint4*)(bSrc0 + (size_t)k0 * Hh);
            bv1 = *(const uint4*)(bSrc1 + (size_t)k0 * Hh);
        }

#pragma unroll
        for (int kk = 0; kk < 2; kk++) {
            int kb = kk * 16;
            unsigned afr[4][4];
#pragma unroll
            for (int mt = 0; mt < 4; mt++) {
                int m = warpM * 64 + mt * 16;
                afr[mt][0] = *(const unsigned*)&As[m + g][kb + 2 * q];
                afr[mt][1] = *(const unsigned*)&As[m + g + 8][kb + 2 * q];
                afr[mt][2] = *(const unsigned*)&As[m + g][kb + 2 * q + 8];
                afr[mt][3] = *(const unsigned*)&As[m + g + 8][kb + 2 * q + 8];
            }
#pragma unroll
            for (int nt = 0; nt < 4; nt++) {
                int n0 = warpN * 32 + nt * 8;
                unsigned bfr[2];
                ldsm_x2_trans(bfr[0], bfr[1], &Bs[kb + (lane & 15)][n0]);
#pragma unroll
                for (int mt = 0; mt < 4; mt++)
                    mma_f16(acc[mt][nt], afr[mt], bfr);
            }
        }
        __syncthreads();
    }

    // ---- epilogue ----
#pragma unroll
    for (int mt = 0; mt < 4; mt++) {
        int r0 = rowBase + warpM * 64 + mt * 16 + g;
        int r1 = r0 + 8;
        bool ok0 = r0 < Nn, ok1 = r1 < Nn;
        float sc0 = (ok0 && scaleFlag) ? g_dinv[r0] : 1.0f;
        float sc1 = (ok1 && scaleFlag) ? g_dinv[r1] : 1.0f;
        int gb0 = (ok0 && poolFlag) ? batch[r0] : 0;
        int gb1 = (ok1 && poolFlag) ? batch[r1] : 0;
#pragma unroll
        for (int nt = 0; nt < 4; nt++) {
            int c = colBase + warpN * 32 + nt * 8 + 2 * q;
            float bs0 = bias[c], bs1 = bias[c + 1];
            float v00 = fmaxf(acc[mt][nt][0] + bs0, 0.0f) * sc0;
            float v01 = fmaxf(acc[mt][nt][1] + bs1, 0.0f) * sc0;
            float v10 = fmaxf(acc[mt][nt][2] + bs0, 0.0f) * sc1;
            float v11 = fmaxf(acc[mt][nt][3] + bs1, 0.0f) * sc1;
            if (poolFlag) {
                if (ok0) {
                    atomicAdd(&g_pool[gb0 * Hh + c], v00);
                    atomicAdd(&g_pool[gb0 * Hh + c + 1], v01);
                }
                if (ok1) {
                    atomicAdd(&g_pool[gb1 * Hh + c], v10);
                    atomicAdd(&g_pool[gb1 * Hh + c + 1], v11);
                }
            } else {
                if (ok0) {
                    __half2 h = __floats2half2_rn(v00, v01);
                    *(__half2*)&C[(size_t)r0 * Hh + c] = h;
                }
                if (ok1) {
                    __half2 h = __floats2half2_rn(v10, v11);
                    *(__half2*)&C[(size_t)r1 * Hh + c] = h;
                }
            }
        }
    }
}

// ---------------- output head -------------------------------------------------
__global__ void out_kernel(const float* __restrict__ Wout,
                           const float* __restrict__ bout,
                           float* __restrict__ out) {
    int g = blockIdx.x;
    int lane = threadIdx.x;                 // 32 threads
    float inv = 1.0f / fmaxf(g_cnts[g], 1.0f);
    float p[8];
#pragma unroll
    for (int v = 0; v < 8; v++) p[v] = g_pool[g * Hh + v * 32 + lane] * inv;
#pragma unroll
    for (int t = 0; t < Tt; t++) {
        float s = 0.0f;
#pragma unroll
        for (int v = 0; v < 8; v++) s += p[v] * Wout[(v * 32 + lane) * Tt + t];
#pragma unroll
        for (int off = 16; off; off >>= 1) s += __shfl_down_sync(0xffffffffu, s, off);
        if (lane == 0) out[g * Tt + t] = s + bout[t];
    }
}

// ---------------- launch -----------------------------------------------------
extern "C" void kernel_launch(void* const* d_in, const int* in_sizes, int n_in,
                              void* d_out, int out_size) {
    const float* x    = (const float*)d_in[0];
    const int*   ei   = (const int*)d_in[1];   // [2, E] int32
    const int*   bat  = (const int*)d_in[2];
    const float* W0 = (const float*)d_in[3];  const float* b0 = (const float*)d_in[4];
    const float* W1 = (const float*)d_in[5];  const float* b1 = (const float*)d_in[6];
    const float* W2 = (const float*)d_in[7];  const float* b2 = (const float*)d_in[8];
    const float* W3 = (const float*)d_in[9];  const float* b3 = (const float*)d_in[10];
    const float* Wout = (const float*)d_in[11]; const float* bout = (const float*)d_in[12];
    float* out = (float*)d_out;

    const int* src = ei;
    const int* dst = ei + Ee;

    // prep (R9 exact)
    zero_wconv_kernel<<<(WTOT + 255) / 256, 256>>>(W0, W1, W2, W3);
    hist_kernel<<<(Ee / 4 + 255) / 256, 256>>>((const int4*)dst);
    scan1_kernel<<<NBLK, 256>>>();
    scan2_kernel<<<1, 256>>>();
    scan3_kernel<<<NBLK, 256>>>(bat);
    fill_kernel<<<(Ee / 4 + 255) / 256, 256>>>((const int4*)src, (const int4*)dst);
    scale_x_kernel<<<(Nn * (Ff / 8) + 255) / 256, 256>>>((const float4*)x);

    dim3 gemmGrid((Nn + BM - 1) / BM, Hh / BN);
    int aggBlocks = (Nn * 32 + 255) / 256;

    __half* W16;
    cudaGetSymbolAddress((void**)&W16, g_W16);

    // layer 0 (K=128)
    agg_kernel<4><<<aggBlocks, 256>>>();
    gemm_f16_kernel<<<gemmGrid, 256>>>(W16 + W0OFF, b0, Ff, 1, 0, bat);
    // layer 1
    agg_kernel<8><<<aggBlocks, 256>>>();
    gemm_f16_kernel<<<gemmGrid, 256>>>(W16 + W1OFF, b1, Hh, 1, 0, bat);
    // layer 2
    agg_kernel<8><<<aggBlocks, 256>>>();
    gemm_f16_kernel<<<gemmGrid, 256>>>(W16 + W2OFF, b2, Hh, 1, 0, bat);
    // layer 3: no dinv pre-scale; fused mean-pool accumulation
    agg_kernel<8><<<aggBlocks, 256>>>();
    gemm_f16_kernel<<<gemmGrid, 256>>>(W16 + W3OFF, b3, Hh, 0, 1, bat);

    // head
    out_kernel<<<Gg, 32>>>(Wout, bout, out);
}

// round 17
// speedup vs baseline: 1.1834x; 1.0714x over previous
#include <cuda_runtime.h>
#include <cuda_fp16.h>

// Problem constants (fixed by the dataset)
#define Nn 50000
#define Ee 800000
#define Ff 128
#define Hh 256
#define Gg 512
#define Tt 5

#define NBLK 196   // ceil(Nn/256) scan blocks

// W16 offsets (halves), [k][n] layout (row-major, n stride 256)
#define W0OFF 0
#define W1OFF 32768
#define W2OFF 98304
#define W3OFF 163840
#define WTOT  229376

// ---------------- scratch (device globals; no allocations allowed) ----------
__device__ int    g_cnt[Nn];
__device__ int    g_rowptr[Nn + 1];
__device__ int    g_cursor[Nn];
__device__ int    g_col[Ee];
__device__ float  g_dinv[Nn];
__device__ int    g_bsum[NBLK];
__device__ int    g_boff[NBLK];
__device__ int    g_gs[Gg];                  // graph node-range start
__device__ int    g_ge[Gg];                  // graph node-range end
__device__ __half g_W16[WTOT];               // fp16 weights, [k][n]
__device__ __half g_bufA[(size_t)Nn * Hh];   // ping (features, fp16)
__device__ __half g_bufB[(size_t)Nn * Hh];   // pong (aggregation output, fp16)

// ---------------- prep kernels ----------------------------------------------
// zero + weight conversion fused (all independent elementwise)
__global__ void zero_wconv_kernel(const float* __restrict__ W0,
                                  const float* __restrict__ W1,
                                  const float* __restrict__ W2,
                                  const float* __restrict__ W3) {
    int i = blockIdx.x * blockDim.x + threadIdx.x;
    if (i < Nn) g_cnt[i] = 0;
    if (i < Gg) { g_gs[i] = 0; g_ge[i] = 0; }
    if (i < WTOT) {
        const float* p; int off;
        if (i < W1OFF)      { p = W0; off = W0OFF; }
        else if (i < W2OFF) { p = W1; off = W1OFF; }
        else if (i < W3OFF) { p = W2; off = W2OFF; }
        else                { p = W3; off = W3OFF; }
        g_W16[i] = __float2half_rn(p[i - off]);
    }
}

__global__ void hist_kernel(const int4* __restrict__ dst4) {
    int e = blockIdx.x * blockDim.x + threadIdx.x;
    if (e < Ee / 4) {
        int4 d = dst4[e];
        if (d.x >= 0 && d.x < Nn) atomicAdd(&g_cnt[d.x], 1);
        if (d.y >= 0 && d.y < Nn) atomicAdd(&g_cnt[d.y], 1);
        if (d.z >= 0 && d.z < Nn) atomicAdd(&g_cnt[d.z], 1);
        if (d.w >= 0 && d.w < Nn) atomicAdd(&g_cnt[d.w], 1);
    }
}

// hierarchical scan: block sums -> scan sums -> per-block rescan
__global__ void scan1_kernel() {
    __shared__ int wsum[8];
    int tid = threadIdx.x, lane = tid & 31, wid = tid >> 5;
    int i = blockIdx.x * 256 + tid;
    int v = (i < Nn) ? g_cnt[i] : 0;
#pragma unroll
    for (int d = 16; d; d >>= 1) v += __shfl_down_sync(0xffffffffu, v, d);
    if (lane == 0) wsum[wid] = v;
    __syncthreads();
    if (tid == 0) {
        int s = 0;
#pragma unroll
        for (int w = 0; w < 8; w++) s += wsum[w];
        g_bsum[blockIdx.x] = s;
    }
}

__global__ void scan2_kernel() {
    __shared__ int s[256];
    int tid = threadIdx.x;
    int v = (tid < NBLK) ? g_bsum[tid] : 0;
    s[tid] = v;
    __syncthreads();
    for (int d = 1; d < 256; d <<= 1) {
        int t = (tid >= d) ? s[tid - d] : 0;
        __syncthreads();
        s[tid] += t;
        __syncthreads();
    }
    if (tid < NBLK) g_boff[tid] = s[tid] - v;   // exclusive
    if (tid == NBLK - 1) g_rowptr[Nn] = s[tid];
}

// scan3 also: dinv, cursor zero, graph boundary detection (batch is sorted)
__global__ void scan3_kernel(const int* __restrict__ batch) {
    __shared__ int wsum[8];
    int tid = threadIdx.x, lane = tid & 31, wid = tid >> 5;
    int i = blockIdx.x * 256 + tid;
    int orig = (i < Nn) ? g_cnt[i] : 0;
    int v = orig;
#pragma unroll
    for (int d = 1; d < 32; d <<= 1) {
        int t = __shfl_up_sync(0xffffffffu, v, d);
        if (lane >= d) v += t;
    }
    if (lane == 31) wsum[wid] = v;
    __syncthreads();
    if (wid == 0 && lane < 8) {
        int s = wsum[lane];
#pragma unroll
        for (int d = 1; d < 8; d <<= 1) {
            int t = __shfl_up_sync(0x000000ffu, s, d);
            if (lane >= d) s += t;
        }
        wsum[lane] = s;
    }
    __syncthreads();
    int prefix = (wid > 0) ? wsum[wid - 1] : 0;
    if (i < Nn) {
        g_rowptr[i] = g_boff[blockIdx.x] + prefix + v - orig;
        g_cursor[i] = 0;
        g_dinv[i] = rsqrtf((float)(orig + 1));   // +1 self-loop
        int b = batch[i];
        if (b >= 0 && b < Gg) {
            int bprev = (i > 0) ? batch[i - 1] : -1;
            int bnext = (i < Nn - 1) ? batch[i + 1] : -2;
            if (bprev != b) g_gs[b] = i;
            if (bnext != b) g_ge[b] = i + 1;
        }
    }
}

__global__ void fill_kernel(const int4* __restrict__ src4,
                            const int4* __restrict__ dst4) {
    int e = blockIdx.x * blockDim.x + threadIdx.x;
    if (e < Ee / 4) {
        int4 d = dst4[e];
        int4 s = src4[e];
#pragma unroll
        for (int j = 0; j < 4; j++) {
            int dd = (&d.x)[j], ss = (&s.x)[j];
            if (dd >= 0 && dd < Nn && ss >= 0 && ss < Nn) {
                int pos = g_rowptr[dd] + atomicAdd(&g_cursor[dd], 1);
                g_col[pos] = ss;
            }
        }
    }
}

// bufA(fp16) = x * dinv[row]   (width Ff); each thread handles 8 floats
__global__ void scale_x_kernel(const float4* __restrict__ x) {
    int idx = blockIdx.x * blockDim.x + threadIdx.x;   // over Nn * 16
    if (idx < Nn * (Ff / 8)) {
        int row = idx >> 4;
        float d = g_dinv[row];
        float4 v0 = x[idx * 2], v1 = x[idx * 2 + 1];
        __half2 h[4];
        h[0] = __floats2half2_rn(v0.x * d, v0.y * d);
        h[1] = __floats2half2_rn(v0.z * d, v0.w * d);
        h[2] = __floats2half2_rn(v1.x * d, v1.y * d);
        h[3] = __floats2half2_rn(v1.z * d, v1.w * d);
        ((uint4*)g_bufA)[idx] = *(uint4*)h;
    }
}

// ---------------- aggregation (fp16 in, fp32 accum, fp16 out) ---------------
// One warp per node, 2-wide edge unroll (R9 exact — measured best).
template <int UC> struct VecT;
template <> struct VecT<2> { using T = uint2; };
template <> struct VecT<4> { using T = uint4; };

template <int VH>
__global__ void agg_kernel() {
    constexpr int UC = VH / 2;
    using V = typename VecT<UC>::T;
    int warp = (blockIdx.x * blockDim.x + threadIdx.x) >> 5;
    int lane = threadIdx.x & 31;
    if (warp >= Nn) return;
    const V* __restrict__ hs = (const V*)g_bufA;   // row = 32 V units
    V* __restrict__ outp = (V*)g_bufB;

    float f[VH];
    {
        V v = hs[(size_t)warp * 32 + lane];        // self-loop term
        const unsigned* u = (const unsigned*)&v;
#pragma unroll
        for (int h = 0; h < UC; h++) {
            float2 p = __half22float2(*(const __half2*)&u[h]);
            f[2 * h] = p.x; f[2 * h + 1] = p.y;
        }
    }

    int beg = g_rowptr[warp], end = g_rowptr[warp + 1];
    int e = beg;
    for (; e + 1 < end; e += 2) {
        int s0 = g_col[e], s1 = g_col[e + 1];
        V v0 = hs[(size_t)s0 * 32 + lane];
        V v1 = hs[(size_t)s1 * 32 + lane];
        const unsigned* u0 = (const unsigned*)&v0;
        const unsigned* u1 = (const unsigned*)&v1;
#pragma unroll
        for (int h = 0; h < UC; h++) {
            float2 p0 = __half22float2(*(const __half2*)&u0[h]);
            float2 p1 = __half22float2(*(const __half2*)&u1[h]);
            f[2 * h] += p0.x + p1.x;
            f[2 * h + 1] += p0.y + p1.y;
        }
    }
    if (e < end) {
        int s0 = g_col[e];
        V v0 = hs[(size_t)s0 * 32 + lane];
        const unsigned* u0 = (const unsigned*)&v0;
#pragma unroll
        for (int h = 0; h < UC; h++) {
            float2 p0 = __half22float2(*(const __half2*)&u0[h]);
            f[2 * h] += p0.x;
            f[2 * h + 1] += p0.y;
        }
    }
    float di = g_dinv[warp];
    V ov;
    unsigned* ou = (unsigned*)&ov;
#pragma unroll
    for (int h = 0; h < UC; h++) {
        __half2 p = __floats2half2_rn(f[2 * h] * di, f[2 * h + 1] * di);
        ou[h] = *(unsigned*)&p;
    }
    outp[(size_t)warp * 32 + lane] = ov;
}

// ---------------- fp16 tensor-core GEMM (R9 exact; pool path removed) --------
#define BM 128
#define BN 128
#define BK 32
#define ASTR 40    // A smem row stride (halves)
#define BNP 136    // B smem row stride (halves)

__device__ __forceinline__ void mma_f16(float* c, const unsigned* a, const unsigned* b) {
    asm volatile(
        "mma.sync.aligned.m16n8k16.row.col.f32.f16.f16.f32 "
        "{%0,%1,%2,%3}, {%4,%5,%6,%7}, {%8,%9}, {%0,%1,%2,%3};"
        : "+f"(c[0]), "+f"(c[1]), "+f"(c[2]), "+f"(c[3])
        : "r"(a[0]), "r"(a[1]), "r"(a[2]), "r"(a[3]), "r"(b[0]), "r"(b[1]));
}

__device__ __forceinline__ void ldsm_x2_trans(unsigned& r0, unsigned& r1, const void* p) {
    unsigned addr = (unsigned)__cvta_generic_to_shared(p);
    asm volatile("ldmatrix.sync.aligned.m8n8.x2.trans.shared.b16 {%0,%1}, [%2];"
                 : "=r"(r0), "=r"(r1) : "r"(addr));
}

__global__ __launch_bounds__(256)
void gemm_f16_kernel(const __half* __restrict__ Wk,   // [K][256] fp16
                     const float* __restrict__ bias,
                     int K, int scaleFlag) {
    __shared__ alignas(16) __half As[BM][ASTR];   // [m][k]
    __shared__ alignas(16) __half Bs[BK][BNP];    // [k][n]

    const __half* __restrict__ A = g_bufB;
    __half* __restrict__ C = g_bufA;

    int tid = threadIdx.x;
    int warpId = tid >> 5, lane = tid & 31;
    int g = lane >> 2, q = lane & 3;
    int warpM = warpId >> 2;          // 0..1  -> 64 rows each
    int warpN = warpId & 3;           // 0..3  -> 32 cols each
    int rowBase = blockIdx.x * BM;
    int colBase = blockIdx.y * BN;

    float acc[4][4][4];
#pragma unroll
    for (int mt = 0; mt < 4; mt++)
#pragma unroll
        for (int nt = 0; nt < 4; nt++)
#pragma unroll
            for (int i = 0; i < 4; i++) acc[mt][nt][i] = 0.0f;

    // A-load indices
    int aRow = tid >> 1;              // 0..127
    int aKoff = (tid & 1) * 16;       // halves
    // B-load indices: coalesced [k][n] copy
    int bK = tid >> 4;                // 0..15
    int bN8 = (tid & 15) * 8;         // n offset, 8 halves per thread

    int gr = rowBase + aRow;
    bool aOk = gr < Nn;
    const __half* aSrc = A + (size_t)gr * K + aKoff;
    const __half* bSrc0 = Wk + (size_t)bK * Hh + colBase + bN8;
    const __half* bSrc1 = Wk + (size_t)(bK + 16) * Hh + colBase + bN8;

    int niter = K / BK;

    // prologue: load iter 0 into regs
    uint4 av0 = make_uint4(0, 0, 0, 0), av1 = av0;
    if (aOk) {
        const uint4* ap = (const uint4*)aSrc;
        av0 = ap[0]; av1 = ap[1];
    }
    uint4 bv0 = *(const uint4*)bSrc0;
    uint4 bv1 = *(const uint4*)bSrc1;

    for (int it = 0; it < niter; it++) {
        // regs -> smem
        *(uint4*)&As[aRow][aKoff] = av0;
        *(uint4*)&As[aRow][aKoff + 8] = av1;
        *(uint4*)&Bs[bK][bN8] = bv0;
        *(uint4*)&Bs[bK + 16][bN8] = bv1;
        __syncthreads();

        // prefetch next iter while computing this one
        if (it + 1 < niter) {
            int k0 = (it + 1) * BK;
            if (aOk) {
                const uint4* ap = (const uint4*)(aSrc + k0);
                av0 = ap[0]; av1 = ap[1];
            }
            bv0 = *(const uint4*)(bSrc0 + (size_t)k0 * Hh);
            bv1 = *(const uint4*)(bSrc1 + (size_t)k0 * Hh);
        }

#pragma unroll
        for (int kk = 0; kk < 2; kk++) {
            int kb = kk * 16;
            unsigned afr[4][4];
#pragma unroll
            for (int mt = 0; mt < 4; mt++) {
                int m = warpM * 64 + mt * 16;
                afr[mt][0] = *(const unsigned*)&As[m + g][kb + 2 * q];
                afr[mt][1] = *(const unsigned*)&As[m + g + 8][kb + 2 * q];
                afr[mt][2] = *(const unsigned*)&As[m + g][kb + 2 * q + 8];
                afr[mt][3] = *(const unsigned*)&As[m + g + 8][kb + 2 * q + 8];
            }
#pragma unroll
            for (int nt = 0; nt < 4; nt++) {
                int n0 = warpN * 32 + nt * 8;
                unsigned bfr[2];
                ldsm_x2_trans(bfr[0], bfr[1], &Bs[kb + (lane & 15)][n0]);
#pragma unroll
                for (int mt = 0; mt < 4; mt++)
                    mma_f16(acc[mt][nt], afr[mt], bfr);
            }
        }
        __syncthreads();
    }

    // ---- epilogue: relu + bias, optional dinv pre-scale, fp16 store ----
#pragma unroll
    for (int mt = 0; mt < 4; mt++) {
        int r0 = rowBase + warpM * 64 + mt * 16 + g;
        int r1 = r0 + 8;
        bool ok0 = r0 < Nn, ok1 = r1 < Nn;
        float sc0 = (ok0 && scaleFlag) ? g_dinv[r0] : 1.0f;
        float sc1 = (ok1 && scaleFlag) ? g_dinv[r1] : 1.0f;
#pragma unroll
        for (int nt = 0; nt < 4; nt++) {
            int c = colBase + warpN * 32 + nt * 8 + 2 * q;
            float bs0 = bias[c], bs1 = bias[c + 1];
            float v00 = fmaxf(acc[mt][nt][0] + bs0, 0.0f) * sc0;
            float v01 = fmaxf(acc[mt][nt][1] + bs1, 0.0f) * sc0;
            float v10 = fmaxf(acc[mt][nt][2] + bs0, 0.0f) * sc1;
            float v11 = fmaxf(acc[mt][nt][3] + bs1, 0.0f) * sc1;
            if (ok0) {
                __half2 h = __floats2half2_rn(v00, v01);
                *(__half2*)&C[(size_t)r0 * Hh + c] = h;
            }
            if (ok1) {
                __half2 h = __floats2half2_rn(v10, v11);
                *(__half2*)&C[(size_t)r1 * Hh + c] = h;
            }
        }
    }
}

// ---------------- fused mean-pool + head (batch sorted -> contiguous rows) ---
// One block per graph, 256 threads = 256 columns. No atomics anywhere.
__global__ __launch_bounds__(256)
void pool_head_kernel(const float* __restrict__ Wout,
                      const float* __restrict__ bout,
                      float* __restrict__ out) {
    __shared__ float red[8][Tt];
    int g = blockIdx.x;
    int c = threadIdx.x;                    // column 0..255
    int lane = c & 31, wid = c >> 5;
    int gs = g_gs[g], ge = g_ge[g];

    const __half* __restrict__ H = g_bufA;  // layer-3 output [Nn][256] fp16
    float s = 0.0f;
    int r = gs;
    for (; r + 1 < ge; r += 2) {
        float a = __half2float(H[(size_t)r * Hh + c]);
        float b = __half2float(H[(size_t)(r + 1) * Hh + c]);
        s += a + b;
    }
    if (r < ge) s += __half2float(H[(size_t)r * Hh + c]);

    float cnt = (float)(ge - gs);
    float pooled = s / fmaxf(cnt, 1.0f);

    float pr[Tt];
#pragma unroll
    for (int t = 0; t < Tt; t++) pr[t] = pooled * Wout[c * Tt + t];
#pragma unroll
    for (int t = 0; t < Tt; t++) {
#pragma unroll
        for (int off = 16; off; off >>= 1)
            pr[t] += __shfl_down_sync(0xffffffffu, pr[t], off);
    }
    if (lane == 0) {
#pragma unroll
        for (int t = 0; t < Tt; t++) red[wid][t] = pr[t];
    }
    __syncthreads();
    if (c < Tt) {
        float acc = 0.0f;
#pragma unroll
        for (int w = 0; w < 8; w++) acc += red[w][c];
        out[g * Tt + c] = acc + bout[c];
    }
}

// ---------------- launch -----------------------------------------------------
extern "C" void kernel_launch(void* const* d_in, const int* in_sizes, int n_in,
                              void* d_out, int out_size) {
    const float* x    = (const float*)d_in[0];
    const int*   ei   = (const int*)d_in[1];   // [2, E] int32
    const int*   bat  = (const int*)d_in[2];
    const float* W0 = (const float*)d_in[3];  const float* b0 = (const float*)d_in[4];
    const float* W1 = (const float*)d_in[5];  const float* b1 = (const float*)d_in[6];
    const float* W2 = (const float*)d_in[7];  const float* b2 = (const float*)d_in[8];
    const float* W3 = (const float*)d_in[9];  const float* b3 = (const float*)d_in[10];
    const float* Wout = (const float*)d_in[11]; const float* bout = (const float*)d_in[12];
    float* out = (float*)d_out;

    const int* src = ei;
    const int* dst = ei + Ee;

    // prep
    zero_wconv_kernel<<<(WTOT + 255) / 256, 256>>>(W0, W1, W2, W3);
    hist_kernel<<<(Ee / 4 + 255) / 256, 256>>>((const int4*)dst);
    scan1_kernel<<<NBLK, 256>>>();
    scan2_kernel<<<1, 256>>>();
    scan3_kernel<<<NBLK, 256>>>(bat);
    fill_kernel<<<(Ee / 4 + 255) / 256, 256>>>((const int4*)src, (const int4*)dst);
    scale_x_kernel<<<(Nn * (Ff / 8) + 255) / 256, 256>>>((const float4*)x);

    dim3 gemmGrid((Nn + BM - 1) / BM, Hh / BN);
    int aggBlocks = (Nn * 32 + 255) / 256;

    __half* W16;
    cudaGetSymbolAddress((void**)&W16, g_W16);

    // layer 0 (K=128)
    agg_kernel<4><<<aggBlocks, 256>>>();
    gemm_f16_kernel<<<gemmGrid, 256>>>(W16 + W0OFF, b0, Ff, 1);
    // layer 1
    agg_kernel<8><<<aggBlocks, 256>>>();
    gemm_f16_kernel<<<gemmGrid, 256>>>(W16 + W1OFF, b1, Hh, 1);
    // layer 2
    agg_kernel<8><<<aggBlocks, 256>>>();
    gemm_f16_kernel<<<gemmGrid, 256>>>(W16 + W2OFF, b2, Hh, 1);
    // layer 3: plain store (no dinv pre-scale, no atomics)
    agg_kernel<8><<<aggBlocks, 256>>>();
    gemm_f16_kernel<<<gemmGrid, 256>>>(W16 + W3OFF, b3, Hh, 0);

    // fused mean-pool + head (sorted batch -> contiguous row ranges)
    pool_head_kernel<<<Gg, 256>>>(Wout, bout, out);
}